// round 14
// baseline (speedup 1.0000x reference)
#include <cuda_runtime.h>
#include <cuda_bf16.h>
#include <cstdint>

typedef unsigned long long ull;

// Problem constants
#define T_STEPS 2048
#define R_DIM   1024
#define B_DIM   8
#define H_DIM   256
#define I_DIM   128
#define NTHR    256

__device__ float g_uin[(size_t)T_STEPS * R_DIM * B_DIM];   // [t][r][b]

// ---------------------------------------------------------------------------
// Helpers
// ---------------------------------------------------------------------------
__device__ __forceinline__ uint32_t smem_u32(const void* p) {
    uint32_t a;
    asm("{ .reg .u64 t; cvta.to.shared.u64 t, %1; cvt.u32.u64 %0, t; }"
        : "=r"(a) : "l"(p));
    return a;
}
__device__ __forceinline__ void st_cluster_f32(uint32_t laddr, int rank, float v) {
    uint32_t rem;
    asm volatile("mapa.shared::cluster.u32 %0, %1, %2;"
                 : "=r"(rem) : "r"(laddr), "r"(rank));
    asm volatile("st.shared::cluster.f32 [%0], %1;" :: "r"(rem), "f"(v) : "memory");
}

__host__ __device__ constexpr int ilog2c(int n) {
    return n <= 1 ? 0 : 1 + ilog2c(n / 2);
}

// f32x2 packed ops (PTX-only FFMA2 path)
__device__ __forceinline__ ull f32x2_fma(ull a, ull b, ull c) {
    ull d;
    asm("fma.rn.f32x2 %0, %1, %2, %3;" : "=l"(d) : "l"(a), "l"(b), "l"(c));
    return d;
}
__device__ __forceinline__ ull f32x2_add(ull a, ull b) {
    ull d;
    asm("add.rn.f32x2 %0, %1, %2;" : "=l"(d) : "l"(a), "l"(b));
    return d;
}
__device__ __forceinline__ float f32x2_hsum(ull v) {
    return __uint_as_float((unsigned)v) + __uint_as_float((unsigned)(v >> 32));
}
__device__ __forceinline__ ulonglong2 ldcg_u2(const ulonglong2* p) {
    ulonglong2 r;
    asm volatile("ld.global.cg.v2.u64 {%0,%1}, [%2];"
                 : "=l"(r.x), "=l"(r.y) : "l"(p));
    return r;
}

// Packed butterfly reduction of N ull (f32x2) values across 32 lanes.
// Post: value index v = lane >> log2(32/N) ends in acc[0] of that lane group.
template <int N>
__device__ __forceinline__ void butterfly_reduce2(ull* acc, int lane) {
    int n = N;
#pragma unroll
    for (int off = 16; off >= 1; off >>= 1) {
        if (n > 1) {
            const int h = n >> 1;
            const bool up = (lane & off) != 0;
#pragma unroll
            for (int i = 0; i < h; ++i) {
                ull send = up ? acc[i] : acc[i + h];
                ull recv = __shfl_xor_sync(0xffffffffu, send, off);
                if (up) acc[i + h] = f32x2_add(acc[i + h], recv);
                else    acc[i]     = f32x2_add(acc[i], recv);
            }
            if (up) {
#pragma unroll
                for (int i = 0; i < h; ++i) acc[i] = acc[i + h];
            }
            n = h;
        } else {
            acc[0] = f32x2_add(acc[0], __shfl_xor_sync(0xffffffffu, acc[0], off));
        }
    }
}

// ---------------------------------------------------------------------------
// Kernel A: uin[t][r][b] = u[b][t][:] . w_in[r][:] + w_bias[r]
// ---------------------------------------------------------------------------
#define UIN_WPAD 132
#define UIN_SMEM (256 * UIN_WPAD * 4 + B_DIM * I_DIM * 4)

__global__ void __launch_bounds__(256) uin_kernel(
    const float* __restrict__ u, const float* __restrict__ w_in,
    const float* __restrict__ w_bias)
{
    extern __shared__ float sm[];
    float* w_s = sm;
    float* u_s = sm + 256 * UIN_WPAD;

    const int tid = threadIdx.x;
    const int r0  = blockIdx.x * 256;
    const int t0  = blockIdx.y * 64;

    for (int j = tid; j < 256 * I_DIM; j += 256) {
        int row = j >> 7, i = j & 127;
        w_s[row * UIN_WPAD + i] = w_in[(r0 + row) * I_DIM + i];
    }
    const float bias = w_bias[r0 + tid];

    for (int tt = 0; tt < 64; ++tt) {
        const int t = t0 + tt;
        __syncthreads();
        for (int j = tid; j < B_DIM * I_DIM; j += 256) {
            int b = j >> 7, i = j & 127;
            u_s[j] = u[((size_t)b * T_STEPS + t) * I_DIM + i];
        }
        __syncthreads();

        float acc[B_DIM];
#pragma unroll
        for (int b = 0; b < B_DIM; ++b) acc[b] = bias;

        const float4* wrow = reinterpret_cast<const float4*>(&w_s[tid * UIN_WPAD]);
#pragma unroll 8
        for (int i4 = 0; i4 < I_DIM / 4; ++i4) {
            float4 w4 = wrow[i4];
#pragma unroll
            for (int b = 0; b < B_DIM; ++b) {
                float4 u4 = reinterpret_cast<const float4*>(&u_s[b * I_DIM])[i4];
                acc[b] = fmaf(w4.x, u4.x, acc[b]);
                acc[b] = fmaf(w4.y, u4.y, acc[b]);
                acc[b] = fmaf(w4.z, u4.z, acc[b]);
                acc[b] = fmaf(w4.w, u4.w, acc[b]);
            }
        }
        float* dst = &g_uin[((size_t)t * R_DIM + r0 + tid) * B_DIM];
        reinterpret_cast<float4*>(dst)[0] = make_float4(acc[0], acc[1], acc[2], acc[3]);
        reinterpret_cast<float4*>(dst)[1] = make_float4(acc[4], acc[5], acc[6], acc[7]);
    }
}

// ---------------------------------------------------------------------------
// Kernel B: cluster-scoped persistent recurrence (R13 winner + K-packed FFMA2).
// K-packing: {w[k],w[k+1]} x {x[k],x[k+1]} pairs are memory-adjacent -> loaded
// directly as ull register pairs, fma.rn.f32x2, horizontal fold at the end.
// ---------------------------------------------------------------------------
#define CPW_OF(CS_)  ((CS_) == 16 ? 3 : 0)
#define ESN_SMEM_F(CS_) ((6144 + CPW_OF(CS_) * 8 * 1024 + (H_DIM/(CS_))*1024 + \
                          (H_DIM/(CS_))*256*2 + (H_DIM/(CS_))) * 4)

// One row x 2 batches K-packed dot product. w2: lane-offset ulonglong2 ptr
// (stride 32 per iter). xp0/xp1: 16 packed K-pairs per batch.
__device__ __forceinline__ void row_mac2(
    const ulonglong2* w2, const ull* xp0, const ull* xp1,
    bool from_global, ull& o0, ull& o1)
{
    ull a0 = 0ull, a1 = 0ull, b0 = 0ull, b1 = 0ull;
#pragma unroll
    for (int i = 0; i < 8; ++i) {
        const ulonglong2 w = from_global ? ldcg_u2(w2 + 32 * i) : w2[32 * i];
        a0 = f32x2_fma(w.x, xp0[2 * i + 0], a0);
        a1 = f32x2_fma(w.y, xp0[2 * i + 1], a1);
        b0 = f32x2_fma(w.x, xp1[2 * i + 0], b0);
        b1 = f32x2_fma(w.y, xp1[2 * i + 1], b1);
    }
    o0 = f32x2_add(a0, a1);
    o1 = f32x2_add(b0, b1);
}

template <int CS>
__global__ void __launch_bounds__(NTHR, 1) esn_cluster(
    const float* __restrict__ w,
    const float* __restrict__ w_pca,
    const float* __restrict__ wzp,
    const float* __restrict__ wzh,
    const float* __restrict__ bz,
    float* __restrict__ out)
{
    constexpr int ROWS = R_DIM / CS;      // W rows per CTA
    constexpr int RPW  = ROWS / 8;        // rows per warp
    constexpr int CPW  = CPW_OF(CS);      // SMEM-cached rows per warp
    constexpr int HC   = H_DIM / CS;      // pca cols / gate rows per CTA
    constexpr int HCW  = HC / 8;          // per warp
    constexpr int NVX  = RPW * 2;         // packed MAC accs per warp
    constexpr int SX   = ilog2c(32 / NVX);
    constexpr int NVP  = HCW * 2;         // packed pca/gate accs per warp
    constexpr int SP   = ilog2c(32 / NVP);

    extern __shared__ float smf[];
    float* x_s    = smf;                       // [2][2][1024]
    float* p_s    = x_s + 4096;                // [2][2][256]
    float* h_s    = p_s + 1024;                // [2][2][256]
    float* wc_s   = h_s + 1024;                // [CPW*8][1024] cached W rows
    float* wpca_s = wc_s + CPW * 8 * 1024;     // [HC][1024]  (transposed)
    float* wzp_s  = wpca_s + HC * 1024;        // [HC][256]
    float* wzh_s  = wzp_s + HC * 256;          // [HC][256]
    float* bz_s   = wzh_s + HC * 256;          // [HC]

    const int tid  = threadIdx.x;
    const int warp = tid >> 5;
    const int lane = tid & 31;
    unsigned cr;
    asm("mov.u32 %0, %%cluster_ctarank;" : "=r"(cr));
    const int crank = (int)cr;
    const int g   = blockIdx.x / CS;
    const int b0  = g * 2;
    const int r0  = crank * ROWS;
    const int hc0 = crank * HC;

    // ---- one-time staging ----
    for (int j = tid; j < 6144; j += NTHR) smf[j] = 0.f;
    if (CPW > 0) {
        for (int idx = tid; idx < CPW * 8 * 256; idx += NTHR) {
            const int rowi = idx >> 8;
            const int q    = idx & 255;
            const int w_   = rowi / CPW;
            const int rr   = rowi % CPW;
            const float4 v4 = *reinterpret_cast<const float4*>(
                &w[(size_t)(r0 + w_ * RPW + rr) * 1024 + 4 * q]);
            *reinterpret_cast<float4*>(&wc_s[rowi * 1024 + 4 * q]) = v4;
        }
    }
    for (int idx = tid; idx < 1024 * (HC / 4); idx += NTHR) {
        const int r = idx / (HC / 4);
        const int q = idx % (HC / 4);
        const float4 v4 = *reinterpret_cast<const float4*>(
            &w_pca[(size_t)r * H_DIM + hc0 + 4 * q]);
        wpca_s[(4 * q + 0) * 1024 + r] = v4.x;
        wpca_s[(4 * q + 1) * 1024 + r] = v4.y;
        wpca_s[(4 * q + 2) * 1024 + r] = v4.z;
        wpca_s[(4 * q + 3) * 1024 + r] = v4.w;
    }
    for (int j = tid; j < HC * 256; j += NTHR) {
        const int row = j >> 8, q = j & 255;
        wzp_s[j] = wzp[(hc0 + row) * H_DIM + q];
        wzh_s[j] = wzh[(hc0 + row) * H_DIM + q];
    }
    if (tid < HC) bz_s[tid] = bz[hc0 + tid];
    __syncthreads();
    asm volatile("barrier.cluster.arrive.aligned;" ::: "memory");
    asm volatile("barrier.cluster.wait.aligned;"   ::: "memory");

    // ---- main loop: gate(t=k-2) | MAC x_k | pca p_{k-1} | barrier ----
    for (int k = 0; k <= T_STEPS + 1; ++k) {
        const bool do_mac  = (k < T_STEPS);
        const bool do_pca  = (k >= 1 && k <= T_STEPS);
        const bool do_gate = (k >= 2);

        // MAC writer mapping: packed value v = lane>>1 -> row v>>1, batch v&1
        const int vx   = lane >> 1;
        const int mrow = vx >> 1;
        const int mb   = vx & 1;
        const int grow = r0 + warp * RPW + mrow;

        float uin_pref = 0.f;
        if (do_mac)
            uin_pref = __ldcg(&g_uin[((size_t)k * R_DIM + grow) * 8 + b0 + mb]);

        // ---- gate for t = k-2 (K-packed) ----
        if (do_gate) {
            const int t = k - 2;
            const float* pv = p_s + (t & 1) * 512;
            const float* hv = h_s + ((t + 1) & 1) * 512;
            const ull* pvu = reinterpret_cast<const ull*>(pv);
            const ull* hvu = reinterpret_cast<const ull*>(hv);
            const ull* wzpu = reinterpret_cast<const ull*>(wzp_s);
            const ull* wzhu = reinterpret_cast<const ull*>(wzh_s);
            const bool have_h = (t > 0);

            ull ga[NVP];
#pragma unroll
            for (int i = 0; i < NVP; ++i) ga[i] = 0ull;
#pragma unroll
            for (int q = 0; q < 4; ++q) {
                const int j = lane + 32 * q;              // ull index in 256-f row
                const ull p0 = pvu[j],       p1 = pvu[128 + j];
                const ull h0 = have_h ? hvu[j] : 0ull;
                const ull h1 = have_h ? hvu[128 + j] : 0ull;
#pragma unroll
                for (int rr = 0; rr < HCW; ++rr) {
                    const int row = warp * HCW + rr;
                    const ull wp = wzpu[row * 128 + j];
                    const ull wh = wzhu[row * 128 + j];
                    ga[rr * 2 + 0] = f32x2_fma(p0, wp, f32x2_fma(h0, wh, ga[rr * 2 + 0]));
                    ga[rr * 2 + 1] = f32x2_fma(p1, wp, f32x2_fma(h1, wh, ga[rr * 2 + 1]));
                }
            }
            butterfly_reduce2<NVP>(ga, lane);
            if ((lane & ((1 << SP) - 1)) == 0) {
                const int v   = lane >> SP;
                const int row = warp * HCW + (v >> 1);
                const int b   = v & 1;
                const int hg  = hc0 + row;
                const float s = f32x2_hsum(ga[0]) + bz_s[row];
                const float z = 1.f / (1.f + __expf(-s));
                const float po = pv[b * 256 + hg];
                const float ho = have_h ? hv[b * 256 + hg] : 0.f;
                const float hn = (1.f - z) * ho + z * po;
                const uint32_t la = smem_u32(&h_s[(t & 1) * 512 + b * 256 + hg]);
#pragma unroll
                for (int rk = 0; rk < CS; ++rk) st_cluster_f32(la, rk, hn);
                out[((size_t)(b0 + b) * T_STEPS + t) * H_DIM + hg] = hn;
            }
        }

        // ---- load x_{k-1} slice as packed K-pairs ----
        ull xp0[16], xp1[16];
        if (do_pca) {
            const ulonglong2* xb0 = reinterpret_cast<const ulonglong2*>(
                x_s + ((k + 1) & 1) * 2048) + lane;
            const ulonglong2* xb1 = reinterpret_cast<const ulonglong2*>(
                x_s + ((k + 1) & 1) * 2048 + 1024) + lane;
#pragma unroll
            for (int i = 0; i < 8; ++i) {
                const ulonglong2 a = xb0[32 * i];
                const ulonglong2 b = xb1[32 * i];
                xp0[2 * i + 0] = a.x; xp0[2 * i + 1] = a.y;
                xp1[2 * i + 0] = b.x; xp1[2 * i + 1] = b.y;
            }
        }

        // ---- reservoir MAC: CPW cached rows (SMEM) + rest streamed (L2) ----
        if (do_mac) {
            ull acc[NVX];
#pragma unroll
            for (int i = 0; i < NVX; ++i) acc[i] = 0ull;
            if (k >= 1) {
#pragma unroll
                for (int rr = 0; rr < CPW; ++rr) {
                    const ulonglong2* w2 = reinterpret_cast<const ulonglong2*>(
                        &wc_s[(warp * CPW + rr) * 1024]) + lane;
                    row_mac2(w2, xp0, xp1, false, acc[rr * 2], acc[rr * 2 + 1]);
                }
#pragma unroll
                for (int rr = CPW; rr < RPW; ++rr) {
                    const ulonglong2* w2 = reinterpret_cast<const ulonglong2*>(
                        w + (size_t)(r0 + warp * RPW + rr) * 1024) + lane;
                    row_mac2(w2, xp0, xp1, true, acc[rr * 2], acc[rr * 2 + 1]);
                }
            }
            butterfly_reduce2<NVX>(acc, lane);
            if ((lane & ((1 << SX) - 1)) == 0) {
                const float val = tanhf(uin_pref + f32x2_hsum(acc[0]));
                const uint32_t la = smem_u32(
                    &x_s[(k & 1) * 2048 + mb * 1024 + grow]);
#pragma unroll
                for (int rk = 0; rk < CS; ++rk) st_cluster_f32(la, rk, val);
            }
        }

        // ---- pca p_{k-1} = x_{k-1} . wpca (SMEM, transposed, K-packed) ----
        if (do_pca) {
            ull pa[NVP];
#pragma unroll
            for (int i = 0; i < NVP; ++i) pa[i] = 0ull;
#pragma unroll
            for (int cc = 0; cc < HCW; ++cc) {
                const ulonglong2* w2 = reinterpret_cast<const ulonglong2*>(
                    &wpca_s[(warp * HCW + cc) * 1024]) + lane;
                row_mac2(w2, xp0, xp1, false, pa[cc * 2], pa[cc * 2 + 1]);
            }
            butterfly_reduce2<NVP>(pa, lane);
            if ((lane & ((1 << SP) - 1)) == 0) {
                const int v   = lane >> SP;
                const int col = warp * HCW + (v >> 1);
                const int b   = v & 1;
                const int hg  = hc0 + col;
                const uint32_t la = smem_u32(
                    &p_s[((k - 1) & 1) * 512 + b * 256 + hg]);
#pragma unroll
                for (int rk = 0; rk < CS; ++rk)
                    st_cluster_f32(la, rk, f32x2_hsum(pa[0]));
            }
        }

        // ---- the ONLY sync: cluster barrier ----
        asm volatile("barrier.cluster.arrive.aligned;" ::: "memory");
        asm volatile("barrier.cluster.wait.aligned;"   ::: "memory");
    }
}

// ---------------------------------------------------------------------------
// Launch: cluster size 16 if allowed, else portable 8.
// ---------------------------------------------------------------------------
extern "C" void kernel_launch(void* const* d_in, const int* in_sizes, int n_in,
                              void* d_out, int out_size) {
    const float* u      = (const float*)d_in[0];
    const float* w_in   = (const float*)d_in[1];
    const float* w      = (const float*)d_in[2];
    const float* w_bias = (const float*)d_in[3];
    const float* w_pca  = (const float*)d_in[4];
    const float* wzp    = (const float*)d_in[5];
    const float* wzh    = (const float*)d_in[6];
    const float* bz     = (const float*)d_in[7];
    float* out = (float*)d_out;

    cudaFuncSetAttribute(uin_kernel,
                         cudaFuncAttributeMaxDynamicSharedMemorySize, UIN_SMEM);
    uin_kernel<<<dim3(4, 32), 256, UIN_SMEM>>>(u, w_in, w_bias);

    cudaFuncSetAttribute(esn_cluster<16>,
                         cudaFuncAttributeMaxDynamicSharedMemorySize,
                         ESN_SMEM_F(16));
    cudaFuncSetAttribute(esn_cluster<16>,
                         cudaFuncAttributeNonPortableClusterSizeAllowed, 1);
    cudaFuncSetAttribute(esn_cluster<8>,
                         cudaFuncAttributeMaxDynamicSharedMemorySize,
                         ESN_SMEM_F(8));

    int maxc = 0;
    {
        cudaLaunchConfig_t probe = {};
        probe.gridDim  = {64, 1, 1};
        probe.blockDim = {NTHR, 1, 1};
        probe.dynamicSmemBytes = ESN_SMEM_F(16);
        cudaError_t e = cudaOccupancyMaxPotentialClusterSize(
            &maxc, (const void*)esn_cluster<16>, &probe);
        if (e != cudaSuccess) { maxc = 0; cudaGetLastError(); }
    }

    cudaLaunchAttribute attrs[1];
    attrs[0].id = cudaLaunchAttributeClusterDimension;
    cudaLaunchConfig_t cfg = {};
    cfg.blockDim = {NTHR, 1, 1};
    cfg.attrs    = attrs;
    cfg.numAttrs = 1;

    if (maxc >= 16) {
        attrs[0].val.clusterDim = {16, 1, 1};
        cfg.gridDim  = {64, 1, 1};
        cfg.dynamicSmemBytes = ESN_SMEM_F(16);
        cudaLaunchKernelEx(&cfg, esn_cluster<16>, w, w_pca, wzp, wzh, bz, out);
    } else {
        attrs[0].val.clusterDim = {8, 1, 1};
        cfg.gridDim  = {32, 1, 1};
        cfg.dynamicSmemBytes = ESN_SMEM_F(8);
        cudaLaunchKernelEx(&cfg, esn_cluster<8>, w, w_pca, wzp, wzh, bz, out);
    }
}